// round 2
// baseline (speedup 1.0000x reference)
#include <cuda_runtime.h>

// CharEmb: per word (B*S=16384): gather char embeddings -> conv1d(k=3, valid)
// over the *reinterpreted* [E=64, C=32] buffer -> maxpool over t -> [word, F=128].
//
// Key identity: torch .view(-1, E, C) on contiguous [C, E] means
//   x[i][c] = flat[i*32+c],  flat[j] = emb[ids[j>>6]][j&63]
// so the smem X tile is a straight flat gather of the embedding rows.

static constexpr int CC = 32;    // chars per word
static constexpr int EE = 64;    // emb dim (conv in-channels)
static constexpr int FF = 128;   // filters
static constexpr int TT = 30;    // C - K + 1
static constexpr int WORDS = 32 * 512;
static constexpr int WPB = 8;    // words per block (processed 2 at a time)
static constexpr int SMEM_FLOATS = EE * 3 * FF + 2 * EE * CC;  // 24576 + 4096
static constexpr int SMEM_BYTES = SMEM_FLOATS * 4;             // 114688

__global__ __launch_bounds__(256, 1) void charconv_kernel(
    const int* __restrict__ ids,    // [WORDS][32]
    const float* __restrict__ emb,  // [101][64]
    const float* __restrict__ w,    // [128][64][3]
    const float* __restrict__ bias, // [128]
    float* __restrict__ out)        // [WORDS][128]
{
    extern __shared__ float sm[];
    float* ws = sm;                  // [192][128]: ws[(i*3+k)*128 + f]
    float* xs = sm + EE * 3 * FF;    // [2][2048]

    const int tid  = threadIdx.x;
    const int f    = tid & 127;      // filter owned by this thread
    const int wsel = tid >> 7;       // which of the 2 concurrent words

    // Stage W transposed: w[f][i][k] -> ws[i*3+k][f] (lanes read consecutive f
    // at compute time -> conflict-free 128B rows).
    for (int idx = tid; idx < FF * EE * 3; idx += 256) {
        int ff   = idx / (EE * 3);
        int rest = idx - ff * (EE * 3);
        ws[rest * FF + ff] = w[idx];
    }
    const float b = __ldg(bias + f);
    __syncthreads();

    float* myx = xs + wsel * (EE * CC);
    const int word0 = blockIdx.x * WPB;

    for (int wp = 0; wp < WPB; wp += 2) {
        const int word = word0 + wp + wsel;
        const int* wid = ids + word * CC;

        // Gather X: 2048 floats = 512 float4, 128 threads x 4 each.
        float4* xv = (float4*)myx;
        #pragma unroll
        for (int j = 0; j < 4; j++) {
            int q  = f + j * 128;          // float4 index 0..511
            int el = q * 4;                // element index 0..2047
            int v  = wid[el >> 6];         // char id for this 64-elem row
            xv[q] = *(const float4*)(emb + v * EE + (el & 63));
        }
        __syncthreads();

        float acc[TT];
        #pragma unroll
        for (int t = 0; t < TT; t++) acc[t] = 0.f;

        #pragma unroll 1   // keep body ~1.6KB, L0 I$-friendly
        for (int i = 0; i < EE; i++) {
            // Broadcast-load row x[i][0..31] (all lanes same address).
            float xr[CC];
            const float4* row = (const float4*)(myx + i * CC);
            #pragma unroll
            for (int q = 0; q < 8; q++) {
                float4 v4 = row[q];
                xr[4*q+0] = v4.x; xr[4*q+1] = v4.y;
                xr[4*q+2] = v4.z; xr[4*q+3] = v4.w;
            }
            const float w0 = ws[(i * 3 + 0) * FF + f];
            const float w1 = ws[(i * 3 + 1) * FF + f];
            const float w2 = ws[(i * 3 + 2) * FF + f];
            #pragma unroll
            for (int t = 0; t < TT; t++)
                acc[t] = fmaf(w2, xr[t + 2],
                         fmaf(w1, xr[t + 1],
                         fmaf(w0, xr[t    ], acc[t])));
        }

        float mx = acc[0];
        #pragma unroll
        for (int t = 1; t < TT; t++) mx = fmaxf(mx, acc[t]);
        out[word * FF + f] = mx + b;

        __syncthreads();  // protect myx before next gather overwrites it
    }
}

extern "C" void kernel_launch(void* const* d_in, const int* in_sizes, int n_in,
                              void* d_out, int out_size) {
    const int*   ids  = (const int*)d_in[0];
    const float* emb  = (const float*)d_in[1];
    const float* w    = (const float*)d_in[2];
    const float* bias = (const float*)d_in[3];
    float*       out  = (float*)d_out;

    // >48KB dynamic smem opt-in (host-side attribute set; idempotent,
    // executes eagerly — not a captured node).
    cudaFuncSetAttribute(charconv_kernel,
                         cudaFuncAttributeMaxDynamicSharedMemorySize, SMEM_BYTES);

    charconv_kernel<<<WORDS / WPB, 256, SMEM_BYTES>>>(ids, emb, w, bias, out);
}

// round 4
// speedup vs baseline: 2.3250x; 2.3250x over previous
#include <cuda_runtime.h>
#include <cstdint>

// CharEmb via mma.sync m16n8k8 tf32 (arch-portable tensor path; tcgen05 is
// sm_103a-only and this toolchain targets base sm_103).
//
// Per word: Y[f][t] = sum_{kappa<192} W[f][kappa] * Xt[kappa][t]
//   W[f][kappa]  = conv_w[f*192 + kappa]            (gmem layout IS A)
//   Xt[kappa][t] = flat[(kappa/3)*32 + t + kappa%3] (t<30; cols 30,31 masked)
//   flat[j]      = emb[ids[word*32 + (j>>6)]][j&63] (torch .view identity)
// out[word][f] = max_t Y + bias[f].

static constexpr int WORDS   = 16384;
static constexpr int WPC     = 16;
static constexpr int GRID    = WORDS / WPC;   // 1024
static constexpr int THREADS = 256;           // 8 warps x 16 filters

// smem: Wfrag [8 wu][24 kt][32 lane] uint4   = 98304 B (tf32 bits, a0..a3)
//       Xfrag [24 kt][4 nt][32 lane] uint2   = 24576 B (tf32 bits, b0,b1)
//       flat  [2048] float                   =  8192 B
static constexpr int WFRAG_BYTES = 8 * 24 * 32 * 16;
static constexpr int XFRAG_OFF   = WFRAG_BYTES;
static constexpr int XFRAG_BYTES = 24 * 4 * 32 * 8;
static constexpr int FLAT_OFF    = XFRAG_OFF + XFRAG_BYTES;
static constexpr int SMEM_TOTAL  = FLAT_OFF + 2048 * 4;   // 131072

__device__ __forceinline__ uint32_t f2tf32(float f) {
    uint32_t r; asm("cvt.rn.tf32.f32 %0, %1;" : "=r"(r) : "f"(f)); return r;
}

__global__ __launch_bounds__(THREADS, 1) void charconv_hmma_kernel(
    const int* __restrict__ ids,    // [WORDS][32]
    const float* __restrict__ wg,   // [128][64][3] == [128][192]
    const float* __restrict__ emb,  // [101][64]
    const float* __restrict__ bias, // [128]
    float* __restrict__ out)        // [WORDS][128]
{
    extern __shared__ char smem[];
    uint32_t* wfs  = (uint32_t*)smem;                 // Wfrag as raw u32
    uint2*    xfs  = (uint2*)(smem + XFRAG_OFF);
    float*    flat = (float*)(smem + FLAT_OFF);

    const int tid  = threadIdx.x;
    const int wu   = tid >> 5;        // warp id: filters [16wu, 16wu+16)
    const int lane = tid & 31;
    const int q    = lane & 3;        // threadID_in_group
    const int g    = lane >> 2;       // groupID

    // ---- stage W fragments: coalesced LDG.128, scatter STS (tf32) ----
    // element idx = f*192 + kappa -> frag slot (wu=f>>4, kt=kappa>>3,
    //   lane=4*(f&7)+(kappa&3), aidx=((f>>3)&1) | ((kappa>>2)&1)<<1)
    {
        const float4* w4 = (const float4*)wg;
        #pragma unroll 1
        for (int j = 0; j < 24; j++) {
            int v4i = tid + j * 256;          // 0..6143
            float4 v = w4[v4i];
            int base = v4i * 4;
            int f    = base / 192;
            int kap0 = base - f * 192;        // multiple of 4, <=188
            int wu_t = f >> 4, r = f & 15;
            float vv[4] = {v.x, v.y, v.z, v.w};
            #pragma unroll
            for (int e = 0; e < 4; e++) {
                int kap  = kap0 + e;
                int kt   = kap >> 3, c4 = kap & 7;
                int ln   = 4 * (r & 7) + (c4 & 3);
                int aidx = (r >> 3) + ((c4 >> 2) << 1);
                wfs[(((wu_t * 24 + kt) * 32 + ln) << 2) + aidx] = f2tf32(vv[e]);
            }
        }
    }
    __syncthreads();

    const float b_lo = bias[wu * 16 + g];
    const float b_hi = bias[wu * 16 + g + 8];
    const int word0  = blockIdx.x * WPC;

    #pragma unroll 1
    for (int wl = 0; wl < WPC; wl++) {
        const int word = word0 + wl;
        const int* wid = ids + word * 32;

        // ---- gather flat[2048]: 512 float4, 2 per thread ----
        #pragma unroll
        for (int j = 0; j < 2; j++) {
            int qq  = tid + j * 256;
            int el  = qq * 4;
            int row = wid[el >> 6];
            *(float4*)(flat + el) = *(const float4*)(emb + row * 64 + (el & 63));
        }
        __syncthreads();

        // ---- build X fragments: slot=(kt,nt,lane) -> {b0,b1} tf32 ----
        #pragma unroll
        for (int j = 0; j < 12; j++) {
            int slot = tid + j * 256;           // 0..3071
            int kt = slot >> 7;
            int nt = (slot >> 5) & 3;
            int l  = slot & 31;
            int t  = 8 * nt + (l >> 2);
            int k0 = 8 * kt + (l & 3);          // b0 kappa; b1 = k0+4
            float v0 = 0.f, v1 = 0.f;
            if (t < 30) {
                int i0 = k0 / 3,       r0 = k0 - i0 * 3;
                int i1 = (k0 + 4) / 3, r1 = (k0 + 4) - i1 * 3;
                v0 = flat[i0 * 32 + t + r0];
                v1 = flat[i1 * 32 + t + r1];
            }
            uint2 st; st.x = f2tf32(v0); st.y = f2tf32(v1);
            xfs[slot] = st;
        }
        __syncthreads();

        // ---- 96 x mma.sync m16n8k8 tf32 ----
        float acc[4][4] = {};                    // [nt][c0..c3]
        const uint4* wfp = (const uint4*)smem + (wu * 24) * 32 + lane;
        const uint2* xfp = (const uint2*)(smem + XFRAG_OFF) + lane;
        #pragma unroll 6
        for (int kt = 0; kt < 24; kt++) {
            uint4 a = wfp[kt * 32];
            #pragma unroll
            for (int nt = 0; nt < 4; nt++) {
                uint2 b = xfp[(kt * 4 + nt) * 32];
                asm volatile(
                    "mma.sync.aligned.m16n8k8.row.col.f32.tf32.tf32.f32 "
                    "{%0,%1,%2,%3},{%4,%5,%6,%7},{%8,%9},{%0,%1,%2,%3};"
                    : "+f"(acc[nt][0]), "+f"(acc[nt][1]),
                      "+f"(acc[nt][2]), "+f"(acc[nt][3])
                    : "r"(a.x), "r"(a.y), "r"(a.z), "r"(a.w),
                      "r"(b.x), "r"(b.y));
            }
        }

        // ---- epilogue: masked max over t, quad shuffle-reduce ----
        // c0:(row g,   t=8nt+2q) c1:(row g,   t+1)
        // c2:(row g+8, t=8nt+2q) c3:(row g+8, t+1)
        float mx0 = -3.0e38f, mx1 = -3.0e38f;
        #pragma unroll
        for (int nt = 0; nt < 4; nt++) {
            int t0 = 8 * nt + 2 * q;
            if (t0 < 30)     { mx0 = fmaxf(mx0, acc[nt][0]);
                               mx1 = fmaxf(mx1, acc[nt][2]); }
            if (t0 + 1 < 30) { mx0 = fmaxf(mx0, acc[nt][1]);
                               mx1 = fmaxf(mx1, acc[nt][3]); }
        }
        mx0 = fmaxf(mx0, __shfl_xor_sync(0xffffffffu, mx0, 1));
        mx0 = fmaxf(mx0, __shfl_xor_sync(0xffffffffu, mx0, 2));
        mx1 = fmaxf(mx1, __shfl_xor_sync(0xffffffffu, mx1, 1));
        mx1 = fmaxf(mx1, __shfl_xor_sync(0xffffffffu, mx1, 2));
        if (q == 0)      out[(size_t)word * 128 + wu * 16 + g]     = mx0 + b_lo;
        else if (q == 1) out[(size_t)word * 128 + wu * 16 + g + 8] = mx1 + b_hi;

        __syncthreads();   // protect flat/xfrag before next word
    }
}

extern "C" void kernel_launch(void* const* d_in, const int* in_sizes, int n_in,
                              void* d_out, int out_size) {
    const int*   ids  = (const int*)d_in[0];
    const float* emb  = (const float*)d_in[1];
    const float* wg   = (const float*)d_in[2];
    const float* bias = (const float*)d_in[3];
    float*       out  = (float*)d_out;

    cudaFuncSetAttribute(charconv_hmma_kernel,
                         cudaFuncAttributeMaxDynamicSharedMemorySize, SMEM_TOTAL);
    charconv_hmma_kernel<<<GRID, THREADS, SMEM_TOTAL>>>(ids, wg, emb, bias, out);
}

// round 6
// speedup vs baseline: 2.9888x; 1.2855x over previous
#include <cuda_runtime.h>
#include <cstdint>

// CharEmb via mma.sync m16n8k8 tf32, v2:
//  - A (weights) lives in registers as MMA fragments (96 regs), loaded once
//    straight from gmem: a0=W[16wu+g][8kt+q], a1=+8row, a2=+4col, a3=both.
//  - double-buffered flat/xfs, gather(w+2) prefetch + build(w+1) interleaved
//    into the MMA(w) loop; one __syncthreads per word.
//  - no t<30 guard in build (padded flat; cols 30/31 masked in epilogue).

static constexpr int WORDS   = 16384;
static constexpr int WPC     = 16;
static constexpr int GRID    = WORDS / WPC;
static constexpr int THREADS = 256;

static constexpr int FLAT_STRIDE = 2056;             // 2048 + pad (reads hit 2049)
static constexpr int XFS_WORD    = 24 * 4 * 32;      // 3072 uint2 slots
static constexpr int FLAT_OFF    = 2 * XFS_WORD * 8; // 49152 B
static constexpr int SMEM_TOTAL  = FLAT_OFF + 2 * FLAT_STRIDE * 4;  // 65600 B

__device__ __forceinline__ uint32_t f2tf32(float f) {
    uint32_t r; asm("cvt.rn.tf32.f32 %0, %1;" : "=r"(r) : "f"(f)); return r;
}

struct U4 { uint32_t x, y, z, w; };

// xfs slot (kt,nt,l): b0 = Xt[8kt+(l&3)][8nt+(l>>2)], b1 = same with k+4,
// where Xt[kappa][t] = flat[(kappa/3)*32 + t + kappa%3].
__device__ __forceinline__ void build_slot(uint2* __restrict__ xN,
                                           const float* __restrict__ fl, int slot) {
    int kt = slot >> 7, nt = (slot >> 5) & 3, l = slot & 31;
    int t  = 8 * nt + (l >> 2);
    int k0 = 8 * kt + (l & 3);
    int i0 = k0 / 3,  r0 = k0 - i0 * 3;
    int k1 = k0 + 4;
    int i1 = k1 / 3,  r1 = k1 - i1 * 3;
    uint2 st;
    st.x = f2tf32(fl[i0 * 32 + t + r0]);
    st.y = f2tf32(fl[i1 * 32 + t + r1]);
    xN[slot] = st;
}

__global__ __launch_bounds__(THREADS, 1) void charconv_hmma2(
    const int* __restrict__ ids,    // [WORDS][32]
    const float* __restrict__ wg,   // [128][192]
    const float* __restrict__ emb,  // [101][64]
    const float* __restrict__ bias, // [128]
    float* __restrict__ out)        // [WORDS][128]
{
    extern __shared__ char smem[];
    uint2* xfs  = (uint2*)smem;
    float* flat = (float*)(smem + FLAT_OFF);

    const int tid  = threadIdx.x;
    const int wu   = tid >> 5, lane = tid & 31;
    const int q    = lane & 3, g = lane >> 2;
    const int word0 = blockIdx.x * WPC;

    // ---- issue gather for word 0 (LDG latency overlapped with A-load) ----
    float4 gv[2];
    {
        const int* wid = ids + word0 * 32;
        #pragma unroll
        for (int j = 0; j < 2; j++) {
            int qq = tid + j * 256;
            gv[j] = *(const float4*)(emb + wid[qq >> 4] * 64 + ((qq * 4) & 63));
        }
    }

    // ---- A fragments -> registers (once) ----
    U4 areg[24];
    {
        const float* w0p = wg + (wu * 16 + g) * 192 + q;
        const float* w1p = w0p + 8 * 192;
        #pragma unroll
        for (int kt = 0; kt < 24; kt++) {
            areg[kt].x = f2tf32(w0p[8 * kt]);
            areg[kt].y = f2tf32(w1p[8 * kt]);
            areg[kt].z = f2tf32(w0p[8 * kt + 4]);
            areg[kt].w = f2tf32(w1p[8 * kt + 4]);
        }
    }

    // flat[0] <- word0
    #pragma unroll
    for (int j = 0; j < 2; j++)
        *(float4*)(flat + (tid + j * 256) * 4) = gv[j];
    __syncthreads();

    // build xfs[0]; gather word1 -> flat[1]
    #pragma unroll
    for (int j = 0; j < 12; j++)
        build_slot(xfs, flat, tid + j * 256);
    {
        const int* wid = ids + (word0 + 1) * 32;
        #pragma unroll
        for (int j = 0; j < 2; j++) {
            int qq = tid + j * 256;
            gv[j] = *(const float4*)(emb + wid[qq >> 4] * 64 + ((qq * 4) & 63));
        }
        #pragma unroll
        for (int j = 0; j < 2; j++)
            *(float4*)(flat + FLAT_STRIDE + (tid + j * 256) * 4) = gv[j];
    }
    __syncthreads();

    const float b_lo = bias[wu * 16 + g];
    const float b_hi = bias[wu * 16 + g + 8];

    #pragma unroll 1
    for (int w = 0; w < WPC; w++) {
        // prefetch gather for word w+2
        const bool pf = (w < WPC - 2);
        float4 pv[2];
        if (pf) {
            const int* wid = ids + (word0 + w + 2) * 32;
            #pragma unroll
            for (int j = 0; j < 2; j++) {
                int qq = tid + j * 256;
                pv[j] = *(const float4*)(emb + wid[qq >> 4] * 64 + ((qq * 4) & 63));
            }
        }

        float acc[4][4] = {};
        const uint2* xb  = xfs + (w & 1) * XFS_WORD + lane;
        uint2*       xN  = xfs + ((w + 1) & 1) * XFS_WORD;
        const float* flN = flat + ((w + 1) & 1) * FLAT_STRIDE;
        const bool bld = (w < WPC - 1);

        #pragma unroll
        for (int kt = 0; kt < 24; kt++) {
            uint2 b[4];
            #pragma unroll
            for (int nt = 0; nt < 4; nt++) b[nt] = xb[(kt * 4 + nt) * 32];
            #pragma unroll
            for (int nt = 0; nt < 4; nt++)
                asm volatile(
                    "mma.sync.aligned.m16n8k8.row.col.f32.tf32.tf32.f32 "
                    "{%0,%1,%2,%3},{%4,%5,%6,%7},{%8,%9},{%0,%1,%2,%3};"
                    : "+f"(acc[nt][0]), "+f"(acc[nt][1]),
                      "+f"(acc[nt][2]), "+f"(acc[nt][3])
                    : "r"(areg[kt].x), "r"(areg[kt].y),
                      "r"(areg[kt].z), "r"(areg[kt].w),
                      "r"(b[nt].x), "r"(b[nt].y));
            if (kt < 12 && bld)                 // interleaved build of word w+1
                build_slot(xN, flN, tid + kt * 256);
        }

        // epilogue: masked max over t, quad shuffle-reduce
        float mx0 = -3.0e38f, mx1 = -3.0e38f;
        #pragma unroll
        for (int nt = 0; nt < 4; nt++) {
            int t0 = 8 * nt + 2 * q;
            if (t0 < 30)     { mx0 = fmaxf(mx0, acc[nt][0]);
                               mx1 = fmaxf(mx1, acc[nt][2]); }
            if (t0 + 1 < 30) { mx0 = fmaxf(mx0, acc[nt][1]);
                               mx1 = fmaxf(mx1, acc[nt][3]); }
        }
        mx0 = fmaxf(mx0, __shfl_xor_sync(0xffffffffu, mx0, 1));
        mx0 = fmaxf(mx0, __shfl_xor_sync(0xffffffffu, mx0, 2));
        mx1 = fmaxf(mx1, __shfl_xor_sync(0xffffffffu, mx1, 1));
        mx1 = fmaxf(mx1, __shfl_xor_sync(0xffffffffu, mx1, 2));
        const int word = word0 + w;
        if (q == 0)      out[(size_t)word * 128 + wu * 16 + g]     = mx0 + b_lo;
        else if (q == 1) out[(size_t)word * 128 + wu * 16 + g + 8] = mx1 + b_hi;

        // flat[w&1] <- word w+2 (buffer free: last read by build in iter w-1)
        if (pf) {
            #pragma unroll
            for (int j = 0; j < 2; j++)
                *(float4*)(flat + (w & 1) * FLAT_STRIDE + (tid + j * 256) * 4) = pv[j];
        }
        __syncthreads();
    }
}

extern "C" void kernel_launch(void* const* d_in, const int* in_sizes, int n_in,
                              void* d_out, int out_size) {
    const int*   ids  = (const int*)d_in[0];
    const float* emb  = (const float*)d_in[1];
    const float* wg   = (const float*)d_in[2];
    const float* bias = (const float*)d_in[3];
    float*       out  = (float*)d_out;

    cudaFuncSetAttribute(charconv_hmma2,
                         cudaFuncAttributeMaxDynamicSharedMemorySize, SMEM_TOTAL);
    charconv_hmma2<<<GRID, THREADS, SMEM_TOTAL>>>(ids, wg, emb, bias, out);
}

// round 7
// speedup vs baseline: 3.3286x; 1.1137x over previous
#include <cuda_runtime.h>
#include <cstdint>

// CharEmb via mma.sync m16n8k8 tf32, v3 — zero shared memory.
// 3 GEMMs sharing one B: Z_k[f][c'] = sum_i W_k[f][i] * G[i][c'], K=64, k=0..2
//   G[i][c'] = emb[ ids[word*32 + (i>>1)] ][ (i&1)*32 + c' ]   (torch .view identity)
//   Y[f][t]  = Z_0[t] + Z_1[t+1] + Z_2[t+2];  out = max_{t<30} Y + bias.
// A_k lives in registers (96 regs). B fragments are LDG'd straight from the
// L1-resident emb table (row ids via __shfl of a register-held id vector).
// Shift-combine epilogue via quad shuffles. No smem, no __syncthreads.

static constexpr int WORDS   = 16384;
static constexpr int WPC     = 16;
static constexpr int GRID    = WORDS / WPC;   // 1024
static constexpr int THREADS = 256;           // 8 warps x 16 filters

__device__ __forceinline__ uint32_t f2tf32(float f) {
    uint32_t r; asm("cvt.rn.tf32.f32 %0, %1;" : "=r"(r) : "f"(f)); return r;
}
struct U4 { uint32_t x, y, z, w; };

__global__ __launch_bounds__(THREADS, 1) void charconv_hmma3(
    const int* __restrict__ ids,    // [WORDS][32]
    const float* __restrict__ wg,   // [128][64][3]
    const float* __restrict__ emb,  // [101][64]
    const float* __restrict__ bias, // [128]
    float* __restrict__ out)        // [WORDS][128]
{
    const int tid  = threadIdx.x;
    const int wu   = tid >> 5, lane = tid & 31;
    const int q    = lane & 3, g = lane >> 2;
    const int word0 = blockIdx.x * WPC;

    // prefetch ids for word 0 while A loads
    int idv = ids[word0 * 32 + lane];

    // ---- A fragments: a[k][kt] for Z_k; A_k[f][i] = wg[f*192 + i*3 + k] ----
    // a0=(row g, i=8kt+q) a1=(+8 rows) a2=(i+4) a3=(both)
    U4 a[3][8];
    {
        const float* r0 = wg + (wu * 16 + g) * 192 + q * 3;
        const float* r1 = r0 + 8 * 192;
        #pragma unroll
        for (int k = 0; k < 3; k++)
            #pragma unroll
            for (int kt = 0; kt < 8; kt++) {
                int o = 24 * kt + k;
                a[k][kt].x = f2tf32(r0[o]);
                a[k][kt].y = f2tf32(r1[o]);
                a[k][kt].z = f2tf32(r0[o + 12]);
                a[k][kt].w = f2tf32(r1[o + 12]);
            }
    }
    const float blo = bias[wu * 16 + g];
    const float bhi = bias[wu * 16 + g + 8];
    const int   eoff = (q & 1) * 32 + g;     // (i&1)*32 + c'-base for this lane

    #pragma unroll 1
    for (int w = 0; w < WPC; w++) {
        int idnext = (w + 1 < WPC) ? ids[(word0 + w + 1) * 32 + lane] : 0;

        float acc[3][4][4] = {};             // [k][nt][c0..c3]

        #pragma unroll
        for (int kt = 0; kt < 8; kt++) {
            // rows for b0 (i=8kt+q_) and b1 (i+4): char m = i>>1
            int m0 = 4 * kt + (q >> 1);
            int r0 = __shfl_sync(0xffffffffu, idv, m0);
            int r1 = __shfl_sync(0xffffffffu, idv, m0 + 2);
            const float* p0 = emb + r0 * 64 + eoff;
            const float* p1 = emb + r1 * 64 + eoff;
            uint32_t b0[4], b1[4];
            #pragma unroll
            for (int nt = 0; nt < 4; nt++) {
                b0[nt] = f2tf32(__ldg(p0 + 8 * nt));
                b1[nt] = f2tf32(__ldg(p1 + 8 * nt));
            }
            #pragma unroll
            for (int k = 0; k < 3; k++)
                #pragma unroll
                for (int nt = 0; nt < 4; nt++)
                    asm volatile(
                        "mma.sync.aligned.m16n8k8.row.col.f32.tf32.tf32.f32 "
                        "{%0,%1,%2,%3},{%4,%5,%6,%7},{%8,%9},{%0,%1,%2,%3};"
                        : "+f"(acc[k][nt][0]), "+f"(acc[k][nt][1]),
                          "+f"(acc[k][nt][2]), "+f"(acc[k][nt][3])
                        : "r"(a[k][kt].x), "r"(a[k][kt].y),
                          "r"(a[k][kt].z), "r"(a[k][kt].w),
                          "r"(b0[nt]), "r"(b1[nt]));
        }

        // ---- epilogue: Y[t] = Z0[t] + Z1[t+1] + Z2[t+2], max over t<30 ----
        // thread (g,q) tile nt holds cols 2q,2q+1 (c0/c1 row g; c2/c3 row g+8).
        // Z1[t0+1] = own c1 of acc[1]; Z2[t0+2], Z1[t0+2], Z2[t0+3] come from
        // quad-neighbor q+1 (tile nt, or nt+1 when q==3).
        const int srcl = (lane & ~3) | ((q + 1) & 3);
        float nB0l[4], nC0l[4], nC1l[4], nB0h[4], nC0h[4], nC1h[4];
        #pragma unroll
        for (int nt = 0; nt < 4; nt++) {
            nB0l[nt] = __shfl_sync(0xffffffffu, acc[1][nt][0], srcl);
            nC0l[nt] = __shfl_sync(0xffffffffu, acc[2][nt][0], srcl);
            nC1l[nt] = __shfl_sync(0xffffffffu, acc[2][nt][1], srcl);
            nB0h[nt] = __shfl_sync(0xffffffffu, acc[1][nt][2], srcl);
            nC0h[nt] = __shfl_sync(0xffffffffu, acc[2][nt][2], srcl);
            nC1h[nt] = __shfl_sync(0xffffffffu, acc[2][nt][3], srcl);
        }
        const bool q3 = (q == 3);
        float mxl = -3.0e38f, mxh = -3.0e38f;
        #pragma unroll
        for (int nt = 0; nt < 4; nt++) {
            if (nt == 3) {
                if (q3) break;               // t0=30/31 invalid
            }
            // select neighbor tile: nt (q<3) or nt+1 (q==3); nt<3 when q3 here
            float c0l = q3 ? nC0l[(nt + 1) & 3] : nC0l[nt];
            float c1l = q3 ? nC1l[(nt + 1) & 3] : nC1l[nt];
            float b0l = q3 ? nB0l[(nt + 1) & 3] : nB0l[nt];
            float c0h = q3 ? nC0h[(nt + 1) & 3] : nC0h[nt];
            float c1h = q3 ? nC1h[(nt + 1) & 3] : nC1h[nt];
            float b0h = q3 ? nB0h[(nt + 1) & 3] : nB0h[nt];
            float Yel = acc[0][nt][0] + acc[1][nt][1] + c0l;   // t = 8nt+2q
            float Yol = acc[0][nt][1] + b0l + c1l;             // t+1
            float Yeh = acc[0][nt][2] + acc[1][nt][3] + c0h;
            float Yoh = acc[0][nt][3] + b0h + c1h;
            mxl = fmaxf(mxl, fmaxf(Yel, Yol));
            mxh = fmaxf(mxh, fmaxf(Yeh, Yoh));
        }
        mxl = fmaxf(mxl, __shfl_xor_sync(0xffffffffu, mxl, 1));
        mxl = fmaxf(mxl, __shfl_xor_sync(0xffffffffu, mxl, 2));
        mxh = fmaxf(mxh, __shfl_xor_sync(0xffffffffu, mxh, 1));
        mxh = fmaxf(mxh, __shfl_xor_sync(0xffffffffu, mxh, 2));
        const int word = word0 + w;
        if (q == 0)      out[(size_t)word * 128 + wu * 16 + g]     = mxl + blo;
        else if (q == 1) out[(size_t)word * 128 + wu * 16 + g + 8] = mxh + bhi;

        idv = idnext;
    }
}

extern "C" void kernel_launch(void* const* d_in, const int* in_sizes, int n_in,
                              void* d_out, int out_size) {
    const int*   ids  = (const int*)d_in[0];
    const float* emb  = (const float*)d_in[1];
    const float* wg   = (const float*)d_in[2];
    const float* bias = (const float*)d_in[3];
    float*       out  = (float*)d_out;

    charconv_hmma3<<<GRID, THREADS>>>(ids, wg, emb, bias, out);
}